// round 1
// baseline (speedup 1.0000x reference)
#include <cuda_runtime.h>

// AugmChamferLoss: B=8, N=4096, D=3 float32.
// P[b,i,j] = ||gts[b,i] - preds[b,j]||^2
// loss_1 = mean over (b,j) of min_i P   -> queries = preds, targets = gts (dir 0)
// loss_2 = mean over (b,i) of min_j P   -> queries = gts, targets = preds (dir 1)
// out = max(loss_1, loss_2)

#define NB      8
#define NPTS    4096
#define THREADS 256
#define NQ_TOTAL (2 * NB * NPTS)            // 65536 queries across both directions
#define BLOCKS   (NQ_TOTAL / THREADS)       // 256
#define NPAIRS   (NPTS / 2)                 // 2048 target pairs
#define SMEM_BYTES (NPTS * 4 * sizeof(float))  // 65536: 4 floats per target

__device__ float g_partials[BLOCKS];

__device__ __forceinline__ unsigned long long pack2(float lo, float hi) {
    unsigned long long r;
    asm("mov.b64 %0, {%1, %2};" : "=l"(r) : "f"(lo), "f"(hi));
    return r;
}
__device__ __forceinline__ unsigned long long ffma2(unsigned long long a,
                                                    unsigned long long b,
                                                    unsigned long long c) {
    unsigned long long d;
    asm("fma.rn.f32x2 %0, %1, %2, %3;" : "=l"(d) : "l"(a), "l"(b), "l"(c));
    return d;
}
__device__ __forceinline__ float2 as_f2(unsigned long long v) {
    float2 f;
    asm("mov.b64 {%0, %1}, %2;" : "=f"(f.x), "=f"(f.y) : "l"(v));
    return f;
}

__global__ void __launch_bounds__(THREADS)
chamfer_min_kernel(const float* __restrict__ preds, const float* __restrict__ gts) {
    extern __shared__ __align__(16) float smem[];
    const int bid = blockIdx.x;
    const int tid = threadIdx.x;
    const int dir   = bid >> 7;        // 0: query=preds, 1: query=gts
    const int r     = bid & 127;
    const int batch = r >> 4;          // 16 blocks per batch per direction
    const int qtile = r & 15;

    const float* qbase = (dir == 0 ? preds : gts) + batch * NPTS * 3;
    const float* tbase = (dir == 0 ? gts : preds) + batch * NPTS * 3;

    // Stage all 4096 targets into smem, transformed to {-2y0,-2y1,-2y2,yy},
    // pair-interleaved SoA: pair p holds 8 floats:
    //   [ -2y0[2p], -2y0[2p+1], -2y1[2p], -2y1[2p+1],
    //     -2y2[2p], -2y2[2p+1],   yy[2p],   yy[2p+1] ]
    // so one ulonglong2 (LDS.128) gives two ready-packed f32x2 operands.
    for (int t = tid; t < NPTS; t += THREADS) {
        const float y0 = tbase[t * 3 + 0];
        const float y1 = tbase[t * 3 + 1];
        const float y2 = tbase[t * 3 + 2];
        const float yy = y0 * y0 + y1 * y1 + y2 * y2;
        const int p = t >> 1, h = t & 1;
        float* dst = smem + p * 8;
        dst[0 + h] = -2.0f * y0;
        dst[2 + h] = -2.0f * y1;
        dst[4 + h] = -2.0f * y2;
        dst[6 + h] = yy;
    }

    // One query per thread.
    const int q = qtile * THREADS + tid;
    const float x0 = qbase[q * 3 + 0];
    const float x1 = qbase[q * 3 + 1];
    const float x2 = qbase[q * 3 + 2];
    const float xx = x0 * x0 + x1 * x1 + x2 * x2;
    const unsigned long long X0 = pack2(x0, x0);
    const unsigned long long X1 = pack2(x1, x1);
    const unsigned long long X2 = pack2(x2, x2);

    __syncthreads();

    const ulonglong2* sp = (const ulonglong2*)smem;
    float bestA = 3.4e38f, bestB = 3.4e38f, bestC = 3.4e38f, bestD = 3.4e38f;

    // 2 pairs (4 targets) per iteration, 4 independent min accumulators
    // to keep the FMNMX dependency chains off the critical path.
#pragma unroll 8
    for (int p = 0; p < NPAIRS; p += 2) {
        const ulonglong2 a0 = sp[2 * p + 0];
        const ulonglong2 b0 = sp[2 * p + 1];
        const ulonglong2 a1 = sp[2 * p + 2];
        const ulonglong2 b1 = sp[2 * p + 3];
        // d = yy + x0*(-2y0) + x1*(-2y1) + x2*(-2y2)   (two targets packed)
        unsigned long long d0 = ffma2(X0, a0.x, b0.y);
        d0 = ffma2(X1, a0.y, d0);
        d0 = ffma2(X2, b0.x, d0);
        unsigned long long d1 = ffma2(X0, a1.x, b1.y);
        d1 = ffma2(X1, a1.y, d1);
        d1 = ffma2(X2, b1.x, d1);
        const float2 f0 = as_f2(d0);
        const float2 f1 = as_f2(d1);
        bestA = fminf(bestA, f0.x);
        bestB = fminf(bestB, f0.y);
        bestC = fminf(bestC, f1.x);
        bestD = fminf(bestD, f1.y);
    }

    const float best = fminf(fminf(bestA, bestB), fminf(bestC, bestD)) + xx;

    // Deterministic block-sum of the 256 per-query mins (reuse smem).
    __syncthreads();
    smem[tid] = best;
    __syncthreads();
#pragma unroll
    for (int s = THREADS / 2; s > 0; s >>= 1) {
        if (tid < s) smem[tid] += smem[tid + s];
        __syncthreads();
    }
    if (tid == 0) g_partials[bid] = smem[0];
}

__global__ void __launch_bounds__(128)
finalize_kernel(float* __restrict__ out) {
    __shared__ float s1[128];
    __shared__ float s2[128];
    const int tid = threadIdx.x;
    s1[tid] = g_partials[tid];         // dir 0 partials -> loss_1 sum
    s2[tid] = g_partials[tid + 128];   // dir 1 partials -> loss_2 sum
    __syncthreads();
#pragma unroll
    for (int s = 64; s > 0; s >>= 1) {
        if (tid < s) {
            s1[tid] += s1[tid + s];
            s2[tid] += s2[tid + s];
        }
        __syncthreads();
    }
    if (tid == 0) {
        const float inv = 1.0f / (float)(NB * NPTS);
        out[0] = fmaxf(s1[0], s2[0]) * inv;
    }
}

extern "C" void kernel_launch(void* const* d_in, const int* in_sizes, int n_in,
                              void* d_out, int out_size) {
    const float* preds = (const float*)d_in[0];
    const float* gts   = (const float*)d_in[1];

    // 64KB dynamic smem needs the opt-in attribute (idempotent, not a stream op).
    cudaFuncSetAttribute(chamfer_min_kernel,
                         cudaFuncAttributeMaxDynamicSharedMemorySize, SMEM_BYTES);

    chamfer_min_kernel<<<BLOCKS, THREADS, SMEM_BYTES>>>(preds, gts);
    finalize_kernel<<<1, 128>>>((float*)d_out);
}

// round 2
// speedup vs baseline: 1.2162x; 1.2162x over previous
#include <cuda_runtime.h>

// AugmChamferLoss: B=8, N=4096, D=3 float32.
// P[b,i,j] = ||gts[b,i] - preds[b,j]||^2
// loss_1 = mean over preds of min over gts   -> queries = preds, targets = gts (dir 0)
// loss_2 = mean over gts  of min over preds  -> queries = gts, targets = preds (dir 1)
// out = max(loss_1, loss_2)
//
// Round 2: query-blocking IQ=2 (each thread owns 2 queries) to amortize every
// broadcast LDS.128 across 2 queries; 128 uniform blocks (1 CTA/SM, one wave).

#define NB      8
#define NPTS    4096
#define THREADS 256
#define IQ      2
#define QPB     (THREADS * IQ)              // 512 queries per block
#define NQ_TOTAL (2 * NB * NPTS)            // 65536 queries (both directions)
#define BLOCKS   (NQ_TOTAL / QPB)           // 128
#define NPAIRS   (NPTS / 2)                 // 2048 target pairs
#define SMEM_BYTES (NPTS * 4 * sizeof(float))  // 65536

__device__ float g_partials[BLOCKS];

__device__ __forceinline__ unsigned long long pack2(float lo, float hi) {
    unsigned long long r;
    asm("mov.b64 %0, {%1, %2};" : "=l"(r) : "f"(lo), "f"(hi));
    return r;
}
__device__ __forceinline__ unsigned long long ffma2(unsigned long long a,
                                                    unsigned long long b,
                                                    unsigned long long c) {
    unsigned long long d;
    asm("fma.rn.f32x2 %0, %1, %2, %3;" : "=l"(d) : "l"(a), "l"(b), "l"(c));
    return d;
}
// Unpack + two-level min in one step: acc = min(acc, min(d.lo, d.hi)).
// The mov.b64 split is elided by ptxas (halves of the pair read directly).
__device__ __forceinline__ void min2_into(float& acc, unsigned long long d) {
    float lo, hi;
    asm("mov.b64 {%0, %1}, %2;" : "=f"(lo), "=f"(hi) : "l"(d));
    acc = fminf(acc, fminf(lo, hi));
}

__global__ void __launch_bounds__(THREADS)
chamfer_min_kernel(const float* __restrict__ preds, const float* __restrict__ gts) {
    extern __shared__ __align__(16) float smem[];
    const int bid = blockIdx.x;
    const int tid = threadIdx.x;
    const int dir    = bid >> 6;       // 64 blocks per direction
    const int r      = bid & 63;
    const int batch  = r >> 3;         // 8 blocks per batch
    const int qchunk = r & 7;          // 512-query chunk within batch

    const float* qbase = (dir == 0 ? preds : gts) + batch * NPTS * 3;
    const float* tbase = (dir == 0 ? gts : preds) + batch * NPTS * 3;

    // Stage all 4096 targets into smem as {-2y0,-2y1,-2y2,yy}, pair-interleaved:
    // pair p: [ -2y0[2p],-2y0[2p+1], -2y1[2p],-2y1[2p+1],
    //           -2y2[2p],-2y2[2p+1],   yy[2p],  yy[2p+1] ]
    // -> one ulonglong2 (LDS.128) = two ready-packed f32x2 operands.
    for (int t = tid; t < NPTS; t += THREADS) {
        const float y0 = tbase[t * 3 + 0];
        const float y1 = tbase[t * 3 + 1];
        const float y2 = tbase[t * 3 + 2];
        const float yy = y0 * y0 + y1 * y1 + y2 * y2;
        const int p = t >> 1, h = t & 1;
        float* dst = smem + p * 8;
        dst[0 + h] = -2.0f * y0;
        dst[2 + h] = -2.0f * y1;
        dst[4 + h] = -2.0f * y2;
        dst[6 + h] = yy;
    }

    // Two queries per thread.
    const int q0 = qchunk * QPB + tid;
    const int q1 = q0 + THREADS;
    const float a0 = qbase[q0 * 3 + 0], a1 = qbase[q0 * 3 + 1], a2 = qbase[q0 * 3 + 2];
    const float b0 = qbase[q1 * 3 + 0], b1 = qbase[q1 * 3 + 1], b2 = qbase[q1 * 3 + 2];
    const float xxa = a0 * a0 + a1 * a1 + a2 * a2;
    const float xxb = b0 * b0 + b1 * b1 + b2 * b2;
    const unsigned long long XA0 = pack2(a0, a0);
    const unsigned long long XA1 = pack2(a1, a1);
    const unsigned long long XA2 = pack2(a2, a2);
    const unsigned long long XB0 = pack2(b0, b0);
    const unsigned long long XB1 = pack2(b1, b1);
    const unsigned long long XB2 = pack2(b2, b2);

    __syncthreads();

    const ulonglong2* sp = (const ulonglong2*)smem;
    float accA0 = 3.4e38f, accA1 = 3.4e38f;   // query 0, two chains
    float accB0 = 3.4e38f, accB1 = 3.4e38f;   // query 1, two chains

    // 2 pairs (4 targets) x 2 queries per iteration:
    // 4 LDS.128 (amortized over both queries), 12 FFMA2, 8 FMNMX.
#pragma unroll 4
    for (int p = 0; p < NPAIRS; p += 2) {
        const ulonglong2 u0 = sp[2 * p + 0];   // pair p:   (-2y0 | -2y1)
        const ulonglong2 v0 = sp[2 * p + 1];   // pair p:   (-2y2 |  yy )
        const ulonglong2 u1 = sp[2 * p + 2];   // pair p+1
        const ulonglong2 v1 = sp[2 * p + 3];

        // d = yy + x0*(-2y0) + x1*(-2y1) + x2*(-2y2), two targets per lane-pair
        unsigned long long dA0 = ffma2(XA0, u0.x, v0.y);
        unsigned long long dB0 = ffma2(XB0, u0.x, v0.y);
        unsigned long long dA1 = ffma2(XA0, u1.x, v1.y);
        unsigned long long dB1 = ffma2(XB0, u1.x, v1.y);
        dA0 = ffma2(XA1, u0.y, dA0);
        dB0 = ffma2(XB1, u0.y, dB0);
        dA1 = ffma2(XA1, u1.y, dA1);
        dB1 = ffma2(XB1, u1.y, dB1);
        dA0 = ffma2(XA2, v0.x, dA0);
        dB0 = ffma2(XB2, v0.x, dB0);
        dA1 = ffma2(XA2, v1.x, dA1);
        dB1 = ffma2(XB2, v1.x, dB1);

        min2_into(accA0, dA0);
        min2_into(accB0, dB0);
        min2_into(accA1, dA1);
        min2_into(accB1, dB1);
    }

    const float bestA = fminf(accA0, accA1) + xxa;
    const float bestB = fminf(accB0, accB1) + xxb;
    const float s = bestA + bestB;   // sum of this thread's two query-mins

    // Deterministic block sum (reuse smem after the loop is done).
    __syncthreads();
    smem[tid] = s;
    __syncthreads();
#pragma unroll
    for (int st = THREADS / 2; st > 0; st >>= 1) {
        if (tid < st) smem[tid] += smem[tid + st];
        __syncthreads();
    }
    if (tid == 0) g_partials[bid] = smem[0];
}

__global__ void __launch_bounds__(64)
finalize_kernel(float* __restrict__ out) {
    __shared__ float s1[64];
    __shared__ float s2[64];
    const int tid = threadIdx.x;
    s1[tid] = g_partials[tid];        // dir 0 -> loss_1 sum
    s2[tid] = g_partials[tid + 64];   // dir 1 -> loss_2 sum
    __syncthreads();
#pragma unroll
    for (int st = 32; st > 0; st >>= 1) {
        if (tid < st) {
            s1[tid] += s1[tid + st];
            s2[tid] += s2[tid + st];
        }
        __syncthreads();
    }
    if (tid == 0) {
        const float inv = 1.0f / (float)(NB * NPTS);
        out[0] = fmaxf(s1[0], s2[0]) * inv;
    }
}

extern "C" void kernel_launch(void* const* d_in, const int* in_sizes, int n_in,
                              void* d_out, int out_size) {
    const float* preds = (const float*)d_in[0];
    const float* gts   = (const float*)d_in[1];

    cudaFuncSetAttribute(chamfer_min_kernel,
                         cudaFuncAttributeMaxDynamicSharedMemorySize, SMEM_BYTES);

    chamfer_min_kernel<<<BLOCKS, THREADS, SMEM_BYTES>>>(preds, gts);
    finalize_kernel<<<1, 64>>>((float*)d_out);
}

// round 5
// speedup vs baseline: 1.3412x; 1.1028x over previous
#include <cuda_runtime.h>

// AugmChamferLoss: B=8, N=4096, D=3 float32.
// P[b,i,j] = ||gts[b,i] - preds[b,j]||^2
// loss_1 = mean over (b,j) of min_i P   (min over gts,  per pred)  -> col-min
// loss_2 = mean over (b,i) of min_j P   (min over preds, per gt )  -> row-min
// out = max(loss_1, loss_2)
//
// Round 5 = round 4 resubmitted (infra failure, never ran): single-pass dual
// reduction with the col-min cross-ty combine fixed.

#define NB       8
#define NPTS     4096
#define THREADS  256
#define NSTRIPS  16
#define CPB      256                   // pred cols per block
#define BLOCKS   (NB * NSTRIPS)        // 128
#define NQ       (NB * NPTS)           // 32768 (denominator for both means)
#define SMEM_FLOATS (1024 + NPTS * 4)  // preds pairs (1024) + gts rows (16384)
#define SMEM_BYTES  (SMEM_FLOATS * 4)  // 69632

__device__ float    g_partials1[BLOCKS];
__device__ unsigned g_rowmin[NB * NPTS];

__device__ __forceinline__ unsigned long long pack2(float lo, float hi) {
    unsigned long long r;
    asm("mov.b64 %0, {%1, %2};" : "=l"(r) : "f"(lo), "f"(hi));
    return r;
}
__device__ __forceinline__ unsigned long long ffma2(unsigned long long a,
                                                    unsigned long long b,
                                                    unsigned long long c) {
    unsigned long long d;
    asm("fma.rn.f32x2 %0, %1, %2, %3;" : "=l"(d) : "l"(a), "l"(b), "l"(c));
    return d;
}
__device__ __forceinline__ unsigned long long add2(unsigned long long a,
                                                   unsigned long long b) {
    unsigned long long d;
    asm("add.rn.f32x2 %0, %1, %2;" : "=l"(d) : "l"(a), "l"(b));
    return d;
}
__device__ __forceinline__ void unpk(unsigned long long v, float& lo, float& hi) {
    asm("mov.b64 {%0, %1}, %2;" : "=f"(lo), "=f"(hi) : "l"(v));
}

// Monotone float -> unsigned map (total order preserved). min is exact and
// order-independent => atomicMin is deterministic.
__device__ __forceinline__ unsigned enc_f(float f) {
    unsigned b = __float_as_uint(f);
    return (b & 0x80000000u) ? ~b : (b | 0x80000000u);
}
__device__ __forceinline__ float dec_f(unsigned u) {
    unsigned b = (u & 0x80000000u) ? (u & 0x7FFFFFFFu) : ~u;
    return __uint_as_float(b);
}

__global__ void __launch_bounds__(512)
init_kernel() {
    g_rowmin[blockIdx.x * 512 + threadIdx.x] = 0xFFFFFFFFu;
}

__global__ void __launch_bounds__(THREADS, 1)
chamfer_kernel(const float* __restrict__ preds, const float* __restrict__ gts) {
    extern __shared__ __align__(16) float smem[];
    float* sp = smem;          // 128 colpairs x 8 floats (packed-pair preds)
    float* sg = smem + 1024;   // 4096 rows x [g0,g1,g2,xx]

    const int tid   = threadIdx.x;
    const int tx    = tid & 15;        // col group (16 cols each)
    const int ty    = tid >> 4;        // row group (256 rows each)
    const int batch = blockIdx.x >> 4;
    const int strip = blockIdx.x & 15;

    const float* pbase = preds + (batch * NPTS + strip * CPB) * 3;
    const float* gbase = gts + batch * NPTS * 3;

    // Stage preds strip: col c -> pair-interleaved {-2p0,-2p1,-2p2,pp}
    {
        const int c = tid;  // 256 cols, 256 threads
        const float p0 = pbase[c * 3 + 0];
        const float p1 = pbase[c * 3 + 1];
        const float p2 = pbase[c * 3 + 2];
        const float pp = p0 * p0 + p1 * p1 + p2 * p2;
        const int cp = c >> 1, h = c & 1;
        float* dst = sp + cp * 8;
        dst[0 + h] = -2.0f * p0;
        dst[2 + h] = -2.0f * p1;
        dst[4 + h] = -2.0f * p2;
        dst[6 + h] = pp;
    }
    // Stage all 4096 gts rows: [g0, g1, g2, xx]
    for (int t = tid; t < NPTS; t += THREADS) {
        const float g0 = gbase[t * 3 + 0];
        const float g1 = gbase[t * 3 + 1];
        const float g2 = gbase[t * 3 + 2];
        float4 v;
        v.x = g0; v.y = g1; v.z = g2;
        v.w = g0 * g0 + g1 * g1 + g2 * g2;
        *(float4*)(sg + t * 4) = v;
    }
    __syncthreads();

    // Cache this thread's 16 pred cols (8 colpairs) in registers.
    const ulonglong2* spp = (const ulonglong2*)(sp) + tx * 16;
    ulonglong2 U[8], V[8];
#pragma unroll
    for (int k = 0; k < 8; k++) {
        U[k] = spp[2 * k + 0];   // (-2p0 pair | -2p1 pair)
        V[k] = spp[2 * k + 1];   // (-2p2 pair |   pp pair)
    }

    float cacc[16];
#pragma unroll
    for (int k = 0; k < 16; k++) cacc[k] = 3.4e38f;

    unsigned* rowmin = g_rowmin + batch * NPTS;

    for (int rb = 0; rb < 32; rb++) {
#pragma unroll
        for (int r = 0; r < 8; r++) {
            const int row = rb * 128 + ty * 8 + r;
            const float4 g = *(const float4*)(sg + row * 4);
            const unsigned long long G0 = pack2(g.x, g.x);
            const unsigned long long G1 = pack2(g.y, g.y);
            const unsigned long long G2 = pack2(g.z, g.z);
            const unsigned long long XX = pack2(g.w, g.w);
            float rm0 = 3.4e38f, rm1 = 3.4e38f;
#pragma unroll
            for (int k = 0; k < 8; k++) {
                // e = pp - 2 g.p  (two cols packed)
                unsigned long long e = ffma2(G2, V[k].x, V[k].y);
                e = ffma2(G1, U[k].y, e);
                e = ffma2(G0, U[k].x, e);
                // row-min on e (xx constant per row, added after min)
                float elo, ehi;
                unpk(e, elo, ehi);
                rm0 = fminf(rm0, elo);
                rm1 = fminf(rm1, ehi);
                // col-min on d = e + xx (xx varies over rows: add before min)
                const unsigned long long d = add2(e, XX);
                float dlo, dhi;
                unpk(d, dlo, dhi);
                cacc[2 * k + 0] = fminf(cacc[2 * k + 0], dlo);
                cacc[2 * k + 1] = fminf(cacc[2 * k + 1], dhi);
            }
            // Combine row-min across the 16 col-threads (half-warp bfly).
            float rm = fminf(rm0, rm1) + g.w;
            rm = fminf(rm, __shfl_xor_sync(0xFFFFFFFFu, rm, 8));
            rm = fminf(rm, __shfl_xor_sync(0xFFFFFFFFu, rm, 4));
            rm = fminf(rm, __shfl_xor_sync(0xFFFFFFFFu, rm, 2));
            rm = fminf(rm, __shfl_xor_sync(0xFFFFFFFFu, rm, 1));
            if (tx == 0) atomicMin(&rowmin[row], enc_f(rm));  // REDG.MIN, exact
        }
    }

    // ---- loss_1 epilogue ----
    // Each column has 16 PARTIAL col-mins (one per ty row-group). Spill to
    // smem [ty][256], min-reduce over ty, THEN sum the 256 true col-mins.
    __syncthreads();             // done reading sg; reuse smem
    float* sc = smem;            // 16 x 256 floats = 16KB
#pragma unroll
    for (int k = 0; k < 16; k++)
        sc[ty * CPB + tx * 16 + k] = cacc[k];
    __syncthreads();
#pragma unroll
    for (int st = 8; st > 0; st >>= 1) {
        if (ty < st) {
#pragma unroll
            for (int k = 0; k < 16; k++) {
                const int c = tx * 16 + k;
                sc[ty * CPB + c] = fminf(sc[ty * CPB + c], sc[(ty + st) * CPB + c]);
            }
        }
        __syncthreads();
    }
    // sc[0..255] now hold the true col-mins for this block's 256 pred cols.
    // Sum them in place (deterministic tree).
#pragma unroll
    for (int st = THREADS / 2; st > 0; st >>= 1) {
        if (tid < st) sc[tid] += sc[tid + st];
        __syncthreads();
    }
    if (tid == 0) g_partials1[blockIdx.x] = sc[0];
}

__global__ void __launch_bounds__(THREADS)
finalize_kernel(float* __restrict__ out) {
    __shared__ float s1[THREADS];
    __shared__ float s2[THREADS];
    const int tid = threadIdx.x;

    float a = 0.0f;
    if (tid < BLOCKS) a = g_partials1[tid];

    float b = 0.0f;
    for (int i = tid; i < NB * NPTS; i += THREADS)   // 128 each, fixed order
        b += dec_f(g_rowmin[i]);

    s1[tid] = a;
    s2[tid] = b;
    __syncthreads();
#pragma unroll
    for (int st = THREADS / 2; st > 0; st >>= 1) {
        if (tid < st) {
            s1[tid] += s1[tid + st];
            s2[tid] += s2[tid + st];
        }
        __syncthreads();
    }
    if (tid == 0) {
        const float inv = 1.0f / (float)NQ;
        out[0] = fmaxf(s1[0], s2[0]) * inv;
    }
}

extern "C" void kernel_launch(void* const* d_in, const int* in_sizes, int n_in,
                              void* d_out, int out_size) {
    const float* preds = (const float*)d_in[0];
    const float* gts   = (const float*)d_in[1];

    cudaFuncSetAttribute(chamfer_kernel,
                         cudaFuncAttributeMaxDynamicSharedMemorySize, SMEM_BYTES);

    init_kernel<<<NB * NPTS / 512, 512>>>();
    chamfer_kernel<<<BLOCKS, THREADS, SMEM_BYTES>>>(preds, gts);
    finalize_kernel<<<1, THREADS>>>((float*)d_out);
}

// round 6
// speedup vs baseline: 1.4737x; 1.0988x over previous
#include <cuda_runtime.h>

// AugmChamferLoss: B=8, N=4096, D=3 float32.
// P[b,i,j] = ||gts[b,i] - preds[b,j]||^2
// loss_1 = mean over (b,j) of min_i P   (col-min, completes in block)
// loss_2 = mean over (b,i) of min_j P   (row-min, combined across strips)
// out = max(loss_1, loss_2)
//
// Round 6: (a) drop init_kernel — row-min combine uses atomicMax under an
// order-reversing float->uint encoding whose identity is 0 (the static init
// value of __device__ globals); (b) 512 threads/block = 4 warps/SMSP to hide
// FFMA2/LDS/SHFL latency (round 5 was latency-bound at 2 warps/SMSP).

#define NB       8
#define NPTS     4096
#define THREADS  512
#define CPB      256                   // pred cols per block
#define BLOCKS   (NB * 16)             // 128: 8 batches x 16 strips
#define NQ       (NB * NPTS)           // 32768
#define SMEM_FLOATS (1024 + NPTS * 4)  // preds pairs (1024) + gts rows (16384)
#define SMEM_BYTES  (SMEM_FLOATS * 4)  // 69632

__device__ float    g_partials1[BLOCKS];
__device__ unsigned g_rowmin[NB * NPTS];   // zero-init = identity for atomicMax

__device__ __forceinline__ unsigned long long pack2(float lo, float hi) {
    unsigned long long r;
    asm("mov.b64 %0, {%1, %2};" : "=l"(r) : "f"(lo), "f"(hi));
    return r;
}
__device__ __forceinline__ unsigned long long ffma2(unsigned long long a,
                                                    unsigned long long b,
                                                    unsigned long long c) {
    unsigned long long d;
    asm("fma.rn.f32x2 %0, %1, %2, %3;" : "=l"(d) : "l"(a), "l"(b), "l"(c));
    return d;
}
__device__ __forceinline__ unsigned long long add2(unsigned long long a,
                                                   unsigned long long b) {
    unsigned long long d;
    asm("add.rn.f32x2 %0, %1, %2;" : "=l"(d) : "l"(a), "l"(b));
    return d;
}
__device__ __forceinline__ void unpk(unsigned long long v, float& lo, float& hi) {
    asm("mov.b64 {%0, %1}, %2;" : "=f"(lo), "=f"(hi) : "l"(v));
}

// Order-REVERSING monotone float<->uint map (self-inverse):
//   f1 < f2  <=>  enc2(f1) > enc2(f2);  enc2(finite) > 0 always.
// => atomicMax over enc2 computes float-min exactly, with 0 as identity.
__device__ __forceinline__ unsigned enc2(float f) {
    unsigned b = __float_as_uint(f);
    return (b & 0x80000000u) ? b : (~b & 0x7FFFFFFFu);
}
__device__ __forceinline__ float dec2(unsigned u) {
    unsigned b = (u & 0x80000000u) ? u : (~u & 0x7FFFFFFFu);
    return __uint_as_float(b);
}

__global__ void __launch_bounds__(THREADS, 1)
chamfer_kernel(const float* __restrict__ preds, const float* __restrict__ gts) {
    extern __shared__ __align__(16) float smem[];
    float* sp = smem;          // 128 colpairs x 8 floats (packed-pair preds)
    float* sg = smem + 1024;   // 4096 rows x [g0,g1,g2,xx]

    const int tid   = threadIdx.x;
    const int tx    = tid & 15;        // col group: 16 cols each
    const int ty    = tid >> 4;        // row group: 32 groups, 128 rows each
    const int batch = blockIdx.x >> 4;
    const int strip = blockIdx.x & 15;

    const float* pbase = preds + (batch * NPTS + strip * CPB) * 3;
    const float* gbase = gts + batch * NPTS * 3;

    // Stage preds strip: col c -> pair-interleaved {-2p0,-2p1,-2p2,pp}
    if (tid < CPB) {
        const int c = tid;
        const float p0 = pbase[c * 3 + 0];
        const float p1 = pbase[c * 3 + 1];
        const float p2 = pbase[c * 3 + 2];
        const float pp = p0 * p0 + p1 * p1 + p2 * p2;
        const int cp = c >> 1, h = c & 1;
        float* dst = sp + cp * 8;
        dst[0 + h] = -2.0f * p0;
        dst[2 + h] = -2.0f * p1;
        dst[4 + h] = -2.0f * p2;
        dst[6 + h] = pp;
    }
    // Stage all 4096 gts rows: [g0, g1, g2, xx]
    for (int t = tid; t < NPTS; t += THREADS) {
        const float g0 = gbase[t * 3 + 0];
        const float g1 = gbase[t * 3 + 1];
        const float g2 = gbase[t * 3 + 2];
        float4 v;
        v.x = g0; v.y = g1; v.z = g2;
        v.w = g0 * g0 + g1 * g1 + g2 * g2;
        *(float4*)(sg + t * 4) = v;
    }
    __syncthreads();

    // Cache this thread's 16 pred cols (8 colpairs) in registers.
    const ulonglong2* spp = (const ulonglong2*)(sp) + tx * 16;
    ulonglong2 U[8], V[8];
#pragma unroll
    for (int k = 0; k < 8; k++) {
        U[k] = spp[2 * k + 0];   // (-2p0 pair | -2p1 pair)
        V[k] = spp[2 * k + 1];   // (-2p2 pair |   pp pair)
    }

    float cacc[16];
#pragma unroll
    for (int k = 0; k < 16; k++) cacc[k] = 3.4e38f;

    unsigned* rowmin = g_rowmin + batch * NPTS;

    for (int rb = 0; rb < 16; rb++) {
#pragma unroll
        for (int r = 0; r < 8; r++) {
            const int row = rb * 256 + ty * 8 + r;
            const float4 g = *(const float4*)(sg + row * 4);
            const unsigned long long G0 = pack2(g.x, g.x);
            const unsigned long long G1 = pack2(g.y, g.y);
            const unsigned long long G2 = pack2(g.z, g.z);
            const unsigned long long XX = pack2(g.w, g.w);
            float rm0 = 3.4e38f, rm1 = 3.4e38f;
#pragma unroll
            for (int k = 0; k < 8; k++) {
                // e = pp - 2 g.p  (two cols packed)
                unsigned long long e = ffma2(G2, V[k].x, V[k].y);
                e = ffma2(G1, U[k].y, e);
                e = ffma2(G0, U[k].x, e);
                // row-min on e (xx constant over the row; added after min)
                float elo, ehi;
                unpk(e, elo, ehi);
                rm0 = fminf(rm0, elo);
                rm1 = fminf(rm1, ehi);
                // col-min on d = e + xx (xx varies over rows: add before min)
                const unsigned long long d = add2(e, XX);
                float dlo, dhi;
                unpk(d, dlo, dhi);
                cacc[2 * k + 0] = fminf(cacc[2 * k + 0], dlo);
                cacc[2 * k + 1] = fminf(cacc[2 * k + 1], dhi);
            }
            // Combine row-min across the 16 col-threads (half-warp bfly).
            float rm = fminf(rm0, rm1) + g.w;
            rm = fminf(rm, __shfl_xor_sync(0xFFFFFFFFu, rm, 8));
            rm = fminf(rm, __shfl_xor_sync(0xFFFFFFFFu, rm, 4));
            rm = fminf(rm, __shfl_xor_sync(0xFFFFFFFFu, rm, 2));
            rm = fminf(rm, __shfl_xor_sync(0xFFFFFFFFu, rm, 1));
            if (tx == 0) atomicMax(&rowmin[row], enc2(rm));  // exact float-min
        }
    }

    // ---- loss_1 epilogue: min over 32 ty-groups, then sum 256 col-mins ----
    __syncthreads();             // done reading sg; reuse smem
    float* sc = smem;            // 32 x 256 floats = 32KB
#pragma unroll
    for (int k = 0; k < 16; k++)
        sc[ty * CPB + tx * 16 + k] = cacc[k];
    __syncthreads();
#pragma unroll
    for (int st = 16; st > 0; st >>= 1) {
        if (ty < st) {
#pragma unroll
            for (int k = 0; k < 16; k++) {
                const int c = tx * 16 + k;
                sc[ty * CPB + c] = fminf(sc[ty * CPB + c], sc[(ty + st) * CPB + c]);
            }
        }
        __syncthreads();
    }
    // sc[0..255] = true col-mins; sum with a deterministic tree.
#pragma unroll
    for (int st = CPB / 2; st > 0; st >>= 1) {
        if (tid < st) sc[tid] += sc[tid + st];
        __syncthreads();
    }
    if (tid == 0) g_partials1[blockIdx.x] = sc[0];
}

__global__ void __launch_bounds__(256)
finalize_kernel(float* __restrict__ out) {
    __shared__ float s1[256];
    __shared__ float s2[256];
    const int tid = threadIdx.x;

    float a = 0.0f;
    if (tid < BLOCKS) a = g_partials1[tid];

    float b = 0.0f;
    for (int i = tid; i < NB * NPTS; i += 256)   // fixed order per thread
        b += dec2(g_rowmin[i]);

    s1[tid] = a;
    s2[tid] = b;
    __syncthreads();
#pragma unroll
    for (int st = 128; st > 0; st >>= 1) {
        if (tid < st) {
            s1[tid] += s1[tid + st];
            s2[tid] += s2[tid + st];
        }
        __syncthreads();
    }
    if (tid == 0) {
        const float inv = 1.0f / (float)NQ;
        out[0] = fmaxf(s1[0], s2[0]) * inv;
    }
}

extern "C" void kernel_launch(void* const* d_in, const int* in_sizes, int n_in,
                              void* d_out, int out_size) {
    const float* preds = (const float*)d_in[0];
    const float* gts   = (const float*)d_in[1];

    cudaFuncSetAttribute(chamfer_kernel,
                         cudaFuncAttributeMaxDynamicSharedMemorySize, SMEM_BYTES);

    chamfer_kernel<<<BLOCKS, THREADS, SMEM_BYTES>>>(preds, gts);
    finalize_kernel<<<1, 256>>>((float*)d_out);
}

// round 7
// speedup vs baseline: 1.4976x; 1.0162x over previous
#include <cuda_runtime.h>

// AugmChamferLoss: B=8, N=4096, D=3 float32.
// P[b,i,j] = ||gts[b,i] - preds[b,j]||^2
// loss_1 = mean over (b,j) of min_i P   (col-min, completes in block)
// loss_2 = mean over (b,i) of min_j P   (row-min, combined across strips)
// out = max(loss_1, loss_2)
//
// Round 7: main kernel unchanged (passing, ~1.4x over fma-pipe floor).
// finalize_kernel rewritten: 1024 threads, uint4 loads, 8-way MLP per thread
// (round 6's 256-thread serial L2 walk cost 10us; target ~2.5us).

#define NB       8
#define NPTS     4096
#define THREADS  512
#define CPB      256                   // pred cols per block
#define BLOCKS   (NB * 16)             // 128: 8 batches x 16 strips
#define NQ       (NB * NPTS)           // 32768
#define SMEM_FLOATS (1024 + NPTS * 4)  // preds pairs (1024) + gts rows (16384)
#define SMEM_BYTES  (SMEM_FLOATS * 4)  // 69632

__device__ float g_partials1[BLOCKS];
__device__ __align__(16) unsigned g_rowmin[NB * NPTS];  // zero-init = atomicMax identity

__device__ __forceinline__ unsigned long long pack2(float lo, float hi) {
    unsigned long long r;
    asm("mov.b64 %0, {%1, %2};" : "=l"(r) : "f"(lo), "f"(hi));
    return r;
}
__device__ __forceinline__ unsigned long long ffma2(unsigned long long a,
                                                    unsigned long long b,
                                                    unsigned long long c) {
    unsigned long long d;
    asm("fma.rn.f32x2 %0, %1, %2, %3;" : "=l"(d) : "l"(a), "l"(b), "l"(c));
    return d;
}
__device__ __forceinline__ unsigned long long add2(unsigned long long a,
                                                   unsigned long long b) {
    unsigned long long d;
    asm("add.rn.f32x2 %0, %1, %2;" : "=l"(d) : "l"(a), "l"(b));
    return d;
}
__device__ __forceinline__ void unpk(unsigned long long v, float& lo, float& hi) {
    asm("mov.b64 {%0, %1}, %2;" : "=f"(lo), "=f"(hi) : "l"(v));
}

// Order-REVERSING monotone float<->uint map (self-inverse):
//   f1 < f2  <=>  enc2(f1) > enc2(f2);  enc2(finite) > 0 always.
// => atomicMax over enc2 computes float-min exactly, with 0 as identity.
__device__ __forceinline__ unsigned enc2(float f) {
    unsigned b = __float_as_uint(f);
    return (b & 0x80000000u) ? b : (~b & 0x7FFFFFFFu);
}
__device__ __forceinline__ float dec2(unsigned u) {
    unsigned b = (u & 0x80000000u) ? u : (~u & 0x7FFFFFFFu);
    return __uint_as_float(b);
}

__global__ void __launch_bounds__(THREADS, 1)
chamfer_kernel(const float* __restrict__ preds, const float* __restrict__ gts) {
    extern __shared__ __align__(16) float smem[];
    float* sp = smem;          // 128 colpairs x 8 floats (packed-pair preds)
    float* sg = smem + 1024;   // 4096 rows x [g0,g1,g2,xx]

    const int tid   = threadIdx.x;
    const int tx    = tid & 15;        // col group: 16 cols each
    const int ty    = tid >> 4;        // row group: 32 groups, 128 rows each
    const int batch = blockIdx.x >> 4;
    const int strip = blockIdx.x & 15;

    const float* pbase = preds + (batch * NPTS + strip * CPB) * 3;
    const float* gbase = gts + batch * NPTS * 3;

    // Stage preds strip: col c -> pair-interleaved {-2p0,-2p1,-2p2,pp}
    if (tid < CPB) {
        const int c = tid;
        const float p0 = pbase[c * 3 + 0];
        const float p1 = pbase[c * 3 + 1];
        const float p2 = pbase[c * 3 + 2];
        const float pp = p0 * p0 + p1 * p1 + p2 * p2;
        const int cp = c >> 1, h = c & 1;
        float* dst = sp + cp * 8;
        dst[0 + h] = -2.0f * p0;
        dst[2 + h] = -2.0f * p1;
        dst[4 + h] = -2.0f * p2;
        dst[6 + h] = pp;
    }
    // Stage all 4096 gts rows: [g0, g1, g2, xx]
    for (int t = tid; t < NPTS; t += THREADS) {
        const float g0 = gbase[t * 3 + 0];
        const float g1 = gbase[t * 3 + 1];
        const float g2 = gbase[t * 3 + 2];
        float4 v;
        v.x = g0; v.y = g1; v.z = g2;
        v.w = g0 * g0 + g1 * g1 + g2 * g2;
        *(float4*)(sg + t * 4) = v;
    }
    __syncthreads();

    // Cache this thread's 16 pred cols (8 colpairs) in registers.
    const ulonglong2* spp = (const ulonglong2*)(sp) + tx * 16;
    ulonglong2 U[8], V[8];
#pragma unroll
    for (int k = 0; k < 8; k++) {
        U[k] = spp[2 * k + 0];   // (-2p0 pair | -2p1 pair)
        V[k] = spp[2 * k + 1];   // (-2p2 pair |   pp pair)
    }

    float cacc[16];
#pragma unroll
    for (int k = 0; k < 16; k++) cacc[k] = 3.4e38f;

    unsigned* rowmin = g_rowmin + batch * NPTS;

    for (int rb = 0; rb < 16; rb++) {
#pragma unroll
        for (int r = 0; r < 8; r++) {
            const int row = rb * 256 + ty * 8 + r;
            const float4 g = *(const float4*)(sg + row * 4);
            const unsigned long long G0 = pack2(g.x, g.x);
            const unsigned long long G1 = pack2(g.y, g.y);
            const unsigned long long G2 = pack2(g.z, g.z);
            const unsigned long long XX = pack2(g.w, g.w);
            float rm0 = 3.4e38f, rm1 = 3.4e38f;
#pragma unroll
            for (int k = 0; k < 8; k++) {
                // e = pp - 2 g.p  (two cols packed)
                unsigned long long e = ffma2(G2, V[k].x, V[k].y);
                e = ffma2(G1, U[k].y, e);
                e = ffma2(G0, U[k].x, e);
                // row-min on e (xx constant over the row; added after min)
                float elo, ehi;
                unpk(e, elo, ehi);
                rm0 = fminf(rm0, elo);
                rm1 = fminf(rm1, ehi);
                // col-min on d = e + xx (xx varies over rows: add before min)
                const unsigned long long d = add2(e, XX);
                float dlo, dhi;
                unpk(d, dlo, dhi);
                cacc[2 * k + 0] = fminf(cacc[2 * k + 0], dlo);
                cacc[2 * k + 1] = fminf(cacc[2 * k + 1], dhi);
            }
            // Combine row-min across the 16 col-threads (half-warp bfly).
            float rm = fminf(rm0, rm1) + g.w;
            rm = fminf(rm, __shfl_xor_sync(0xFFFFFFFFu, rm, 8));
            rm = fminf(rm, __shfl_xor_sync(0xFFFFFFFFu, rm, 4));
            rm = fminf(rm, __shfl_xor_sync(0xFFFFFFFFu, rm, 2));
            rm = fminf(rm, __shfl_xor_sync(0xFFFFFFFFu, rm, 1));
            if (tx == 0) atomicMax(&rowmin[row], enc2(rm));  // exact float-min
        }
    }

    // ---- loss_1 epilogue: min over 32 ty-groups, then sum 256 col-mins ----
    __syncthreads();             // done reading sg; reuse smem
    float* sc = smem;            // 32 x 256 floats = 32KB
#pragma unroll
    for (int k = 0; k < 16; k++)
        sc[ty * CPB + tx * 16 + k] = cacc[k];
    __syncthreads();
#pragma unroll
    for (int st = 16; st > 0; st >>= 1) {
        if (ty < st) {
#pragma unroll
            for (int k = 0; k < 16; k++) {
                const int c = tx * 16 + k;
                sc[ty * CPB + c] = fminf(sc[ty * CPB + c], sc[(ty + st) * CPB + c]);
            }
        }
        __syncthreads();
    }
    // sc[0..255] = true col-mins; sum with a deterministic tree.
#pragma unroll
    for (int st = CPB / 2; st > 0; st >>= 1) {
        if (tid < st) sc[tid] += sc[tid + st];
        __syncthreads();
    }
    if (tid == 0) g_partials1[blockIdx.x] = sc[0];
}

__global__ void __launch_bounds__(1024)
finalize_kernel(float* __restrict__ out) {
    __shared__ float s1[1024];
    __shared__ float s2[1024];
    const int tid = threadIdx.x;

    float a = (tid < BLOCKS) ? g_partials1[tid] : 0.0f;

    // 32768 rowmins = 8192 uint4; 1024 threads x 8 vec-loads, 4 accumulators.
    const uint4* rm = (const uint4*)g_rowmin;
    float b0 = 0.0f, b1 = 0.0f, b2 = 0.0f, b3 = 0.0f;
#pragma unroll
    for (int i = 0; i < 8; i++) {
        const uint4 v = rm[tid + i * 1024];
        b0 += dec2(v.x);
        b1 += dec2(v.y);
        b2 += dec2(v.z);
        b3 += dec2(v.w);
    }
    const float b = (b0 + b1) + (b2 + b3);

    s1[tid] = a;
    s2[tid] = b;
    __syncthreads();
#pragma unroll
    for (int st = 512; st > 0; st >>= 1) {
        if (tid < st) {
            s1[tid] += s1[tid + st];
            s2[tid] += s2[tid + st];
        }
        __syncthreads();
    }
    if (tid == 0) {
        const float inv = 1.0f / (float)NQ;
        out[0] = fmaxf(s1[0], s2[0]) * inv;
    }
}

extern "C" void kernel_launch(void* const* d_in, const int* in_sizes, int n_in,
                              void* d_out, int out_size) {
    const float* preds = (const float*)d_in[0];
    const float* gts   = (const float*)d_in[1];

    cudaFuncSetAttribute(chamfer_kernel,
                         cudaFuncAttributeMaxDynamicSharedMemorySize, SMEM_BYTES);

    chamfer_kernel<<<BLOCKS, THREADS, SMEM_BYTES>>>(preds, gts);
    finalize_kernel<<<1, 1024>>>((float*)d_out);
}